// round 13
// baseline (speedup 1.0000x reference)
#include <cuda_runtime.h>
#include <cstdint>

#define BATCHN 4096
#define INSZ   1024
#define HUN    512
#define GN     2048
#define SHID   4096
#define OHID   2048

#define BK     32                     // f32 per K-chunk
#define NSTAGE 3
#define ASTR   36                     // u32 per smem row (32 + 4 pad)
#define TILEU  (128*ASTR)             // 4608 u32 per tile
#define STGU   (2*TILEU)              // 9216 u32 = 36864 B per stage
#define SMEM_BYTES (NSTAGE*STGU*4)    // 110592 B (C tile 128*132*4=67584 fits)

// Scratch (device globals: allocation-free)
__device__ float g_h0[(size_t)4 * BATCHN * HUN];
__device__ float g_X2[(size_t)4 * BATCHN * INSZ];

__device__ __forceinline__ void cp16(uint32_t s, const void* g) {
    asm volatile("cp.async.ca.shared.global [%0], [%1], 16;\n" :: "r"(s), "l"(g));
}
__device__ __forceinline__ void cpcommit() { asm volatile("cp.async.commit_group;\n" ::: "memory"); }
template <int N> __device__ __forceinline__ void cpwait() {
    asm volatile("cp.async.wait_group %0;\n" :: "n"(N) : "memory");
}
__device__ __forceinline__ void ldsm4(uint32_t* r, uint32_t addr) {
    asm volatile("ldmatrix.sync.aligned.m8n8.x4.shared.b16 {%0,%1,%2,%3}, [%4];\n"
                 : "=r"(r[0]), "=r"(r[1]), "=r"(r[2]), "=r"(r[3]) : "r"(addr));
}
__device__ __forceinline__ void mma8(float* c, const uint32_t* a, const uint32_t* b) {
    asm volatile(
        "mma.sync.aligned.m16n8k8.row.col.f32.tf32.tf32.f32 "
        "{%0,%1,%2,%3}, {%4,%5,%6,%7}, {%8,%9}, {%0,%1,%2,%3};\n"
        : "+f"(c[0]), "+f"(c[1]), "+f"(c[2]), "+f"(c[3])
        : "r"(a[0]), "r"(a[1]), "r"(a[2]), "r"(a[3]), "r"(b[0]), "r"(b[1]));
}
__device__ __forceinline__ float sigm(float x) { return 1.f / (1.f + __expf(-x)); }

// 4 warps as 2(M) x 2(N); warp tile 64 x 64. acc[4][8][4] = 128 regs.
__device__ __forceinline__ void compute_stage(uint32_t sA, uint32_t sB,
                                              int wm, int wn, int lane,
                                              float acc[4][8][4])
{
    const int q = lane >> 3, jj = lane & 7;
    #pragma unroll
    for (int ks = 0; ks < 4; ks++) {
        uint32_t a[4][4], b[4][4];
        #pragma unroll
        for (int mt = 0; mt < 4; mt++) {
            int r = wm * 64 + mt * 16 + (q & 1) * 8 + jj;
            ldsm4(a[mt], sA + (uint32_t)(r * ASTR + ks * 8 + (q >> 1) * 4) * 4);
        }
        #pragma unroll
        for (int nt = 0; nt < 4; nt++) {
            int c = wn * 64 + nt * 16 + (q >> 1) * 8 + jj;
            ldsm4(b[nt], sB + (uint32_t)(c * ASTR + ks * 8 + (q & 1) * 4) * 4);
        }
        #pragma unroll
        for (int mt = 0; mt < 4; mt++)
            #pragma unroll
            for (int nt = 0; nt < 4; nt++) {
                mma8(acc[mt][2 * nt],     a[mt], &b[nt][0]);
                mma8(acc[mt][2 * nt + 1], a[mt], &b[nt][2]);
            }
    }
}

// ---------------------------------------------------------------------------
// gates kernel: 128 rows x (4 gates x 32 hidden) per CTA, (depth d, stack j).
// GEMM: [X | hx] @ [Wih | Whh]^T, K = 1536.
// ---------------------------------------------------------------------------
__global__ __launch_bounds__(128, 2) void gates_kernel(
    const float* __restrict__ input, const float* __restrict__ state,
    const float* __restrict__ Wih, const float* __restrict__ Whh,
    const float* __restrict__ bih, const float* __restrict__ bhh,
    int j, float* __restrict__ out_ho, float* __restrict__ out_state)
{
    extern __shared__ uint32_t dynsmem[];
    const uint32_t smbase = (uint32_t)__cvta_generic_to_shared(dynsmem);

    const int tid  = threadIdx.x;
    const int lane = tid & 31;
    const int wid  = tid >> 5;
    const int wm   = wid >> 1;      // 0..1
    const int wn   = wid & 1;       // 0..1
    const int d    = blockIdx.z;
    const int m0   = blockIdx.y * 128;
    const int hblk = blockIdx.x;    // 32 hidden units

    const float* X   = (j == 0) ? input : (g_X2 + (size_t)d * BATCHN * INSZ);
    const float* Wi  = Wih + (size_t)(d * 2 + j) * GN * INSZ;
    const float* Wh  = Whh + (size_t)(d * 2 + j) * GN * HUN;
    const float* hxb = state + (size_t)j * BATCHN * SHID + (size_t)d * HUN;

    // Thread tid owns A row tid and B row tid (8 x 16B chunks each per stage)
    const float* srcAX = X   + (size_t)(m0 + tid) * INSZ;
    const float* srcAH = hxb + (size_t)(m0 + tid) * SHID;
    const int wr = (tid >> 5) * HUN + hblk * 32 + (tid & 31);   // gathered gate row
    const float* srcBX = Wi + (size_t)wr * INSZ;
    const float* srcBH = Wh + (size_t)wr * HUN;
    const uint32_t dstA = smbase + (uint32_t)(tid * ASTR) * 4;
    const uint32_t dstB = smbase + (uint32_t)(TILEU + tid * ASTR) * 4;

    auto load_stage = [&](int kt, int s) {
        const uint32_t so = (uint32_t)(s * STGU * 4);
        const int k0 = kt * BK;
        if (k0 < INSZ) {
            #pragma unroll
            for (int q = 0; q < 8; q++) cp16(dstA + so + q * 16, srcAX + k0 + q * 4);
            #pragma unroll
            for (int q = 0; q < 8; q++) cp16(dstB + so + q * 16, srcBX + k0 + q * 4);
        } else {
            const int kh = k0 - INSZ;
            #pragma unroll
            for (int q = 0; q < 8; q++) cp16(dstA + so + q * 16, srcAH + kh + q * 4);
            #pragma unroll
            for (int q = 0; q < 8; q++) cp16(dstB + so + q * 16, srcBH + kh + q * 4);
        }
    };

    float acc[4][8][4];
    #pragma unroll
    for (int a = 0; a < 4; a++)
        #pragma unroll
        for (int b = 0; b < 8; b++)
            #pragma unroll
            for (int c = 0; c < 4; c++) acc[a][b][c] = 0.f;

    const int NT = 1536 / BK;   // 48
    load_stage(0, 0); cpcommit();
    load_stage(1, 1); cpcommit();
    cpwait<1>();
    __syncthreads();

    #pragma unroll 1
    for (int kt = 0; kt < NT; kt++) {
        const int s = kt % NSTAGE;
        const uint32_t sA = smbase + (uint32_t)(s * STGU * 4);
        compute_stage(sA, sA + TILEU * 4, wm, wn, lane, acc);
        const int kn = kt + 2;
        if (kn < NT) load_stage(kn, kn % NSTAGE);
        cpcommit();
        cpwait<1>();
        __syncthreads();
    }

    // Scatter accumulators to smem C tile [128][132]
    float* Csm = (float*)dynsmem;
    const int gid = lane >> 2, t4 = lane & 3;
    #pragma unroll
    for (int mt = 0; mt < 4; mt++)
        #pragma unroll
        for (int nt = 0; nt < 8; nt++) {
            int r = wm * 64 + mt * 16 + gid;
            int c = wn * 64 + nt * 8 + 2 * t4;
            Csm[r * 132 + c]           = acc[mt][nt][0];
            Csm[r * 132 + c + 1]       = acc[mt][nt][1];
            Csm[(r + 8) * 132 + c]     = acc[mt][nt][2];
            Csm[(r + 8) * 132 + c + 1] = acc[mt][nt][3];
        }
    __syncthreads();

    // LSTM epilogue: 128 rows x 32 hidden; 32 (m,h) pairs per thread.
    const int hl = tid & 31;
    const int hg = hblk * 32 + hl;
    const size_t bb = (size_t)(d * 2 + j) * GN;
    const float bi0 = bih[bb + hg]           + bhh[bb + hg];
    const float bf0 = bih[bb + HUN + hg]     + bhh[bb + HUN + hg];
    const float bg0 = bih[bb + 2 * HUN + hg] + bhh[bb + 2 * HUN + hg];
    const float bo0 = bih[bb + 3 * HUN + hg] + bhh[bb + 3 * HUN + hg];
    const int colO = d * HUN + hg;

    #pragma unroll 4
    for (int p = 0; p < 32; p++) {
        const int idx = p * 128 + tid;
        const int m = idx >> 5;
        const int row = m0 + m;

        float gi = Csm[m * 132 + hl]      + bi0;
        float gf = Csm[m * 132 + 32 + hl] + bf0;
        float gg = Csm[m * 132 + 64 + hl] + bg0;
        float go = Csm[m * 132 + 96 + hl] + bo0;

        float i_ = sigm(gi), f_ = sigm(gf), g_ = tanhf(gg), o_ = sigm(go);

        float cx = state[((size_t)(2 + j) * BATCHN + row) * SHID + colO];
        float cn = f_ * cx + i_ * g_;
        float hn = o_ * tanhf(cn);
        float hx = state[((size_t)j * BATCHN + row) * SHID + colO];
        float hs = hn + hx;

        if (out_state) {
            out_state[((size_t)j * BATCHN + row) * OHID + colO] = hs;
            out_state[((size_t)(2 + j) * BATCHN + row) * OHID + colO] = cn;
        }
        if (j == 1) {
            if (out_ho) out_ho[(size_t)row * OHID + colO] = hs;
        } else {
            g_h0[((size_t)d * BATCHN + row) * HUN + hg] = hn;
        }
    }
}

// ---------------------------------------------------------------------------
// proj kernel: X2[d] = input + h0[d] @ projW^T + projb  (M=4096, N=1024, K=512)
// ---------------------------------------------------------------------------
__global__ __launch_bounds__(128, 2) void proj_kernel(
    const float* __restrict__ projW, const float* __restrict__ projb,
    const float* __restrict__ input)
{
    extern __shared__ uint32_t dynsmem[];
    const uint32_t smbase = (uint32_t)__cvta_generic_to_shared(dynsmem);

    const int tid  = threadIdx.x;
    const int lane = tid & 31;
    const int wid  = tid >> 5;
    const int wm   = wid >> 1;
    const int wn   = wid & 1;
    const int d    = blockIdx.z;
    const int m0   = blockIdx.y * 128;
    const int nblk = blockIdx.x;

    const float* A = g_h0 + (size_t)d * BATCHN * HUN;
    const float* srcA = A + (size_t)(m0 + tid) * HUN;
    const float* srcB = projW + (size_t)(nblk * 128 + tid) * HUN;
    const uint32_t dstA = smbase + (uint32_t)(tid * ASTR) * 4;
    const uint32_t dstB = smbase + (uint32_t)(TILEU + tid * ASTR) * 4;

    auto load_stage = [&](int kt, int s) {
        const uint32_t so = (uint32_t)(s * STGU * 4);
        const int k0 = kt * BK;
        #pragma unroll
        for (int q = 0; q < 8; q++) cp16(dstA + so + q * 16, srcA + k0 + q * 4);
        #pragma unroll
        for (int q = 0; q < 8; q++) cp16(dstB + so + q * 16, srcB + k0 + q * 4);
    };

    float acc[4][8][4];
    #pragma unroll
    for (int a = 0; a < 4; a++)
        #pragma unroll
        for (int b = 0; b < 8; b++)
            #pragma unroll
            for (int c = 0; c < 4; c++) acc[a][b][c] = 0.f;

    const int NT = 512 / BK;   // 16
    load_stage(0, 0); cpcommit();
    load_stage(1, 1); cpcommit();
    cpwait<1>();
    __syncthreads();

    #pragma unroll 1
    for (int kt = 0; kt < NT; kt++) {
        const int s = kt % NSTAGE;
        const uint32_t sA = smbase + (uint32_t)(s * STGU * 4);
        compute_stage(sA, sA + TILEU * 4, wm, wn, lane, acc);
        const int kn = kt + 2;
        if (kn < NT) load_stage(kn, kn % NSTAGE);
        cpcommit();
        cpwait<1>();
        __syncthreads();
    }

    float* Csm = (float*)dynsmem;
    const int gid = lane >> 2, t4 = lane & 3;
    #pragma unroll
    for (int mt = 0; mt < 4; mt++)
        #pragma unroll
        for (int nt = 0; nt < 8; nt++) {
            int r = wm * 64 + mt * 16 + gid;
            int c = wn * 64 + nt * 8 + 2 * t4;
            Csm[r * 132 + c]           = acc[mt][nt][0];
            Csm[r * 132 + c + 1]       = acc[mt][nt][1];
            Csm[(r + 8) * 132 + c]     = acc[mt][nt][2];
            Csm[(r + 8) * 132 + c + 1] = acc[mt][nt][3];
        }
    __syncthreads();

    // Epilogue: thread = column, iterate 128 rows.
    const int col = nblk * 128 + tid;
    const float pb = projb[col];
    float* x2c = g_X2 + (size_t)d * BATCHN * INSZ + col;
    #pragma unroll 4
    for (int m = 0; m < 128; m++) {
        const int row = m0 + m;
        float v = Csm[m * 132 + tid] + pb + input[(size_t)row * INSZ + col];
        x2c[(size_t)row * INSZ] = v;
    }
}

extern "C" void kernel_launch(void* const* d_in, const int* in_sizes, int n_in,
                              void* d_out, int out_size)
{
    const float* input = (const float*)d_in[0];
    const float* state = (const float*)d_in[1];
    const float* Wih   = (const float*)d_in[2];
    const float* Whh   = (const float*)d_in[3];
    const float* bih   = (const float*)d_in[4];
    const float* bhh   = (const float*)d_in[5];
    const float* projW = (const float*)d_in[6];
    const float* projb = (const float*)d_in[7];

    float* out = (float*)d_out;
    const size_t HO_ELEMS = (size_t)BATCHN * OHID;
    const size_t ST_ELEMS = (size_t)4 * BATCHN * OHID;

    float* out_ho = nullptr;
    float* out_state = nullptr;
    if ((size_t)out_size >= HO_ELEMS + ST_ELEMS) {
        out_ho = out;
        out_state = out + HO_ELEMS;
    } else if ((size_t)out_size == ST_ELEMS) {
        out_state = out;
    } else {
        out_ho = out;
    }

    cudaFuncSetAttribute(gates_kernel, cudaFuncAttributeMaxDynamicSharedMemorySize, SMEM_BYTES);
    cudaFuncSetAttribute(proj_kernel,  cudaFuncAttributeMaxDynamicSharedMemorySize, SMEM_BYTES);

    dim3 blk(128);
    gates_kernel<<<dim3(16, 32, 4), blk, SMEM_BYTES>>>(input, state, Wih, Whh, bih, bhh,
                                                       0, out_ho, out_state);
    proj_kernel<<<dim3(8, 32, 4), blk, SMEM_BYTES>>>(projW, projb, input);
    gates_kernel<<<dim3(16, 32, 4), blk, SMEM_BYTES>>>(input, state, Wih, Whh, bih, bhh,
                                                       1, out_ho, out_state);
}

// round 14
// speedup vs baseline: 1.8380x; 1.8380x over previous
#include <cuda_runtime.h>
#include <cstdint>

#define BATCHN 4096
#define INSZ   1024
#define HUN    512
#define GN     2048
#define SHID   4096
#define OHID   2048

#define BK     32                     // f32 per K-chunk
#define NSTAGE 3
#define ASTR   36                     // u32 per smem row (32 + 4 pad)
#define TILEU  (128*ASTR)             // 4608 u32 per tile
#define STGU   (2*TILEU)              // 9216 u32 = 36864 B per stage
#define SMEM_BYTES (NSTAGE*STGU*4)    // 110592 B (C tile 128*132*4=67584 fits)

// Scratch (device globals: allocation-free)
__device__ float g_h0[(size_t)4 * BATCHN * HUN];
__device__ float g_X2[(size_t)4 * BATCHN * INSZ];

__device__ __forceinline__ void cp16(uint32_t s, const void* g) {
    asm volatile("cp.async.cg.shared.global [%0], [%1], 16;\n" :: "r"(s), "l"(g));
}
__device__ __forceinline__ void cpcommit() { asm volatile("cp.async.commit_group;\n" ::: "memory"); }
template <int N> __device__ __forceinline__ void cpwait() {
    asm volatile("cp.async.wait_group %0;\n" :: "n"(N) : "memory");
}
__device__ __forceinline__ void ldsm4(uint32_t* r, uint32_t addr) {
    asm volatile("ldmatrix.sync.aligned.m8n8.x4.shared.b16 {%0,%1,%2,%3}, [%4];\n"
                 : "=r"(r[0]), "=r"(r[1]), "=r"(r[2]), "=r"(r[3]) : "r"(addr));
}
__device__ __forceinline__ void mma8(float* c, const uint32_t* a, const uint32_t* b) {
    asm volatile(
        "mma.sync.aligned.m16n8k8.row.col.f32.tf32.tf32.f32 "
        "{%0,%1,%2,%3}, {%4,%5,%6,%7}, {%8,%9}, {%0,%1,%2,%3};\n"
        : "+f"(c[0]), "+f"(c[1]), "+f"(c[2]), "+f"(c[3])
        : "r"(a[0]), "r"(a[1]), "r"(a[2]), "r"(a[3]), "r"(b[0]), "r"(b[1]));
}
__device__ __forceinline__ float sigm(float x) { return 1.f / (1.f + __expf(-x)); }

// 8 warps as 4(M) x 2(N); warp tile 32 x 64 (R7 proven layout).
__device__ __forceinline__ void compute_stage(uint32_t sA, uint32_t sB,
                                              int wm, int wn, int lane,
                                              float acc[2][8][4])
{
    const int q = lane >> 3, jj = lane & 7;
    #pragma unroll
    for (int ks = 0; ks < 4; ks++) {
        uint32_t a[2][4], b[4][4];
        #pragma unroll
        for (int mt = 0; mt < 2; mt++) {
            // quads: q0:(rows+0,k+0) q1:(rows+8,k+0) q2:(rows+0,k+4) q3:(rows+8,k+4)
            int r = wm * 32 + mt * 16 + (q & 1) * 8 + jj;
            ldsm4(a[mt], sA + (uint32_t)(r * ASTR + ks * 8 + (q >> 1) * 4) * 4);
        }
        #pragma unroll
        for (int nt = 0; nt < 4; nt++) {
            // quads: q0:(cols+0,k+0) q1:(cols+0,k+4) q2:(cols+8,k+0) q3:(cols+8,k+4)
            int c = wn * 64 + nt * 16 + (q >> 1) * 8 + jj;
            ldsm4(b[nt], sB + (uint32_t)(c * ASTR + ks * 8 + (q & 1) * 4) * 4);
        }
        #pragma unroll
        for (int mt = 0; mt < 2; mt++)
            #pragma unroll
            for (int nt = 0; nt < 4; nt++) {
                mma8(acc[mt][2 * nt],     a[mt], &b[nt][0]);
                mma8(acc[mt][2 * nt + 1], a[mt], &b[nt][2]);
            }
    }
}

// ---------------------------------------------------------------------------
// gates kernel: 128 rows x (4 gates x 32 hidden) per CTA, (depth d, stack j).
// GEMM: [X | hx] @ [Wih | Whh]^T, K = 1536.
// ---------------------------------------------------------------------------
__global__ __launch_bounds__(256, 2) void gates_kernel(
    const float* __restrict__ input, const float* __restrict__ state,
    const float* __restrict__ Wih, const float* __restrict__ Whh,
    const float* __restrict__ bih, const float* __restrict__ bhh,
    int j, float* __restrict__ out_ho, float* __restrict__ out_state)
{
    extern __shared__ uint32_t dynsmem[];
    const uint32_t smbase = (uint32_t)__cvta_generic_to_shared(dynsmem);

    const int tid  = threadIdx.x;
    const int lane = tid & 31;
    const int wid  = tid >> 5;
    const int wm   = wid >> 1;      // 0..3
    const int wn   = wid & 1;       // 0..1
    const int d    = blockIdx.z;
    const int m0   = blockIdx.y * 128;
    const int hblk = blockIdx.x;    // 32 hidden units

    const float* X   = (j == 0) ? input : (g_X2 + (size_t)d * BATCHN * INSZ);
    const float* Wi  = Wih + (size_t)(d * 2 + j) * GN * INSZ;
    const float* Wh  = Whh + (size_t)(d * 2 + j) * GN * HUN;
    const float* hxb = state + (size_t)j * BATCHN * SHID + (size_t)d * HUN;

    // Per stage: A = 1024 16B-chunks, B = 1024 16B-chunks; 4 of each per thread.
    const float* srcAX[4]; const float* srcAH[4]; uint32_t dstA[4];
    const float* srcBX[4]; const float* srcBH[4]; uint32_t dstB[4];
    #pragma unroll
    for (int u = 0; u < 4; u++) {
        int id = tid + u * 256;
        int r = id >> 3, qq = id & 7;                    // row, 16B-chunk
        srcAX[u] = X   + (size_t)(m0 + r) * INSZ + qq * 4;
        srcAH[u] = hxb + (size_t)(m0 + r) * SHID + qq * 4;
        dstA[u]  = smbase + (uint32_t)(r * ASTR + qq * 4) * 4;
        int wr = (r >> 5) * HUN + hblk * 32 + (r & 31);  // gathered gate row
        srcBX[u] = Wi + (size_t)wr * INSZ + qq * 4;
        srcBH[u] = Wh + (size_t)wr * HUN + qq * 4;
        dstB[u]  = smbase + (uint32_t)(TILEU + r * ASTR + qq * 4) * 4;
    }

    auto load_stage = [&](int kt, int s) {
        const uint32_t so = (uint32_t)(s * STGU * 4);
        const int k0 = kt * BK;
        if (k0 < INSZ) {
            #pragma unroll
            for (int u = 0; u < 4; u++) cp16(dstA[u] + so, srcAX[u] + k0);
            #pragma unroll
            for (int u = 0; u < 4; u++) cp16(dstB[u] + so, srcBX[u] + k0);
        } else {
            const int kh = k0 - INSZ;
            #pragma unroll
            for (int u = 0; u < 4; u++) cp16(dstA[u] + so, srcAH[u] + kh);
            #pragma unroll
            for (int u = 0; u < 4; u++) cp16(dstB[u] + so, srcBH[u] + kh);
        }
    };

    float acc[2][8][4];
    #pragma unroll
    for (int a = 0; a < 2; a++)
        #pragma unroll
        for (int b = 0; b < 8; b++)
            #pragma unroll
            for (int c = 0; c < 4; c++) acc[a][b][c] = 0.f;

    const int NT = 1536 / BK;   // 48
    load_stage(0, 0); cpcommit();
    load_stage(1, 1); cpcommit();

    #pragma unroll 1
    for (int kt = 0; kt < NT; kt++) {
        cpwait<1>();             // stage kt resident (kt, kt+1 in flight)
        __syncthreads();         // all warps done with stage kt-1 (slot being refilled)
        const int kn = kt + 2;
        if (kn < NT) { load_stage(kn, kn % NSTAGE); cpcommit(); }
        const uint32_t sA = smbase + (uint32_t)((kt % NSTAGE) * STGU * 4);
        compute_stage(sA, sA + TILEU * 4, wm, wn, lane, acc);
    }
    __syncthreads();

    // Scatter accumulators to smem C tile [128][132]
    float* Csm = (float*)dynsmem;
    const int gid = lane >> 2, t4 = lane & 3;
    #pragma unroll
    for (int mt = 0; mt < 2; mt++)
        #pragma unroll
        for (int nt = 0; nt < 8; nt++) {
            int r = wm * 32 + mt * 16 + gid;
            int c = wn * 64 + nt * 8 + 2 * t4;
            Csm[r * 132 + c]           = acc[mt][nt][0];
            Csm[r * 132 + c + 1]       = acc[mt][nt][1];
            Csm[(r + 8) * 132 + c]     = acc[mt][nt][2];
            Csm[(r + 8) * 132 + c + 1] = acc[mt][nt][3];
        }
    __syncthreads();

    // LSTM epilogue: 128 rows x 32 hidden; 16 (m,h) pairs per thread.
    const int hl = tid & 31;
    const int hg = hblk * 32 + hl;
    const size_t bb = (size_t)(d * 2 + j) * GN;
    const float bi0 = bih[bb + hg]           + bhh[bb + hg];
    const float bf0 = bih[bb + HUN + hg]     + bhh[bb + HUN + hg];
    const float bg0 = bih[bb + 2 * HUN + hg] + bhh[bb + 2 * HUN + hg];
    const float bo0 = bih[bb + 3 * HUN + hg] + bhh[bb + 3 * HUN + hg];
    const int colO = d * HUN + hg;

    #pragma unroll 4
    for (int p = 0; p < 16; p++) {
        const int idx = p * 256 + tid;
        const int m = idx >> 5;
        const int row = m0 + m;

        float gi = Csm[m * 132 + hl]      + bi0;
        float gf = Csm[m * 132 + 32 + hl] + bf0;
        float gg = Csm[m * 132 + 64 + hl] + bg0;
        float go = Csm[m * 132 + 96 + hl] + bo0;

        float i_ = sigm(gi), f_ = sigm(gf), g_ = tanhf(gg), o_ = sigm(go);

        float cx = state[((size_t)(2 + j) * BATCHN + row) * SHID + colO];
        float cn = f_ * cx + i_ * g_;
        float hn = o_ * tanhf(cn);
        float hx = state[((size_t)j * BATCHN + row) * SHID + colO];
        float hs = hn + hx;

        if (out_state) {
            out_state[((size_t)j * BATCHN + row) * OHID + colO] = hs;
            out_state[((size_t)(2 + j) * BATCHN + row) * OHID + colO] = cn;
        }
        if (j == 1) {
            if (out_ho) out_ho[(size_t)row * OHID + colO] = hs;
        } else {
            g_h0[((size_t)d * BATCHN + row) * HUN + hg] = hn;
        }
    }
}

// ---------------------------------------------------------------------------
// proj kernel: X2[d] = input + h0[d] @ projW^T + projb  (M=4096, N=1024, K=512)
// ---------------------------------------------------------------------------
__global__ __launch_bounds__(256, 2) void proj_kernel(
    const float* __restrict__ projW, const float* __restrict__ projb,
    const float* __restrict__ input)
{
    extern __shared__ uint32_t dynsmem[];
    const uint32_t smbase = (uint32_t)__cvta_generic_to_shared(dynsmem);

    const int tid  = threadIdx.x;
    const int lane = tid & 31;
    const int wid  = tid >> 5;
    const int wm   = wid >> 1;
    const int wn   = wid & 1;
    const int d    = blockIdx.z;
    const int m0   = blockIdx.y * 128;
    const int nblk = blockIdx.x;

    const float* A = g_h0 + (size_t)d * BATCHN * HUN;

    const float* srcA[4]; uint32_t dstA[4];
    const float* srcB[4]; uint32_t dstB[4];
    #pragma unroll
    for (int u = 0; u < 4; u++) {
        int id = tid + u * 256;
        int r = id >> 3, qq = id & 7;
        srcA[u] = A + (size_t)(m0 + r) * HUN + qq * 4;
        dstA[u] = smbase + (uint32_t)(r * ASTR + qq * 4) * 4;
        srcB[u] = projW + (size_t)(nblk * 128 + r) * HUN + qq * 4;
        dstB[u] = smbase + (uint32_t)(TILEU + r * ASTR + qq * 4) * 4;
    }

    auto load_stage = [&](int kt, int s) {
        const uint32_t so = (uint32_t)(s * STGU * 4);
        const int k0 = kt * BK;
        #pragma unroll
        for (int u = 0; u < 4; u++) cp16(dstA[u] + so, srcA[u] + k0);
        #pragma unroll
        for (int u = 0; u < 4; u++) cp16(dstB[u] + so, srcB[u] + k0);
    };

    float acc[2][8][4];
    #pragma unroll
    for (int a = 0; a < 2; a++)
        #pragma unroll
        for (int b = 0; b < 8; b++)
            #pragma unroll
            for (int c = 0; c < 4; c++) acc[a][b][c] = 0.f;

    const int NT = 512 / BK;   // 16
    load_stage(0, 0); cpcommit();
    load_stage(1, 1); cpcommit();

    #pragma unroll 1
    for (int kt = 0; kt < NT; kt++) {
        cpwait<1>();
        __syncthreads();
        const int kn = kt + 2;
        if (kn < NT) { load_stage(kn, kn % NSTAGE); cpcommit(); }
        const uint32_t sA = smbase + (uint32_t)((kt % NSTAGE) * STGU * 4);
        compute_stage(sA, sA + TILEU * 4, wm, wn, lane, acc);
    }
    __syncthreads();

    float* Csm = (float*)dynsmem;
    const int gid = lane >> 2, t4 = lane & 3;
    #pragma unroll
    for (int mt = 0; mt < 2; mt++)
        #pragma unroll
        for (int nt = 0; nt < 8; nt++) {
            int r = wm * 32 + mt * 16 + gid;
            int c = wn * 64 + nt * 8 + 2 * t4;
            Csm[r * 132 + c]           = acc[mt][nt][0];
            Csm[r * 132 + c + 1]       = acc[mt][nt][1];
            Csm[(r + 8) * 132 + c]     = acc[mt][nt][2];
            Csm[(r + 8) * 132 + c + 1] = acc[mt][nt][3];
        }
    __syncthreads();

    const int cl  = tid & 127;
    const int col = nblk * 128 + cl;
    const float pb = projb[col];
    #pragma unroll 4
    for (int p = 0; p < 64; p++) {
        const int idx = p * 256 + tid;
        const int m = idx >> 7;
        const int row = m0 + m;
        float v = Csm[m * 132 + cl] + pb + input[(size_t)row * INSZ + col];
        g_X2[((size_t)d * BATCHN + row) * INSZ + col] = v;
    }
}

extern "C" void kernel_launch(void* const* d_in, const int* in_sizes, int n_in,
                              void* d_out, int out_size)
{
    const float* input = (const float*)d_in[0];
    const float* state = (const float*)d_in[1];
    const float* Wih   = (const float*)d_in[2];
    const float* Whh   = (const float*)d_in[3];
    const float* bih   = (const float*)d_in[4];
    const float* bhh   = (const float*)d_in[5];
    const float* projW = (const float*)d_in[6];
    const float* projb = (const float*)d_in[7];

    float* out = (float*)d_out;
    const size_t HO_ELEMS = (size_t)BATCHN * OHID;
    const size_t ST_ELEMS = (size_t)4 * BATCHN * OHID;

    float* out_ho = nullptr;
    float* out_state = nullptr;
    if ((size_t)out_size >= HO_ELEMS + ST_ELEMS) {
        out_ho = out;
        out_state = out + HO_ELEMS;
    } else if ((size_t)out_size == ST_ELEMS) {
        out_state = out;
    } else {
        out_ho = out;
    }

    cudaFuncSetAttribute(gates_kernel, cudaFuncAttributeMaxDynamicSharedMemorySize, SMEM_BYTES);
    cudaFuncSetAttribute(proj_kernel,  cudaFuncAttributeMaxDynamicSharedMemorySize, SMEM_BYTES);

    dim3 blk(256);
    gates_kernel<<<dim3(16, 32, 4), blk, SMEM_BYTES>>>(input, state, Wih, Whh, bih, bhh,
                                                       0, out_ho, out_state);
    proj_kernel<<<dim3(8, 32, 4), blk, SMEM_BYTES>>>(projW, projb, input);
    gates_kernel<<<dim3(16, 32, 4), blk, SMEM_BYTES>>>(input, state, Wih, Whh, bih, bhh,
                                                       1, out_ho, out_state);
}